// round 15
// baseline (speedup 1.0000x reference)
#include <cuda_runtime.h>
#include <cuda_fp16.h>
#include <mma.h>
#include <cstdint>

using namespace nvcuda;

#define NN 50000
#define EE 800000
#define SCAN_B 1024
#define NBLK ((NN + SCAN_B - 1) / SCAN_B)   // 49

// ---------------- scratch ----------------
__device__ __align__(16) int    g_hist[NN];        // zero at load; self-zeroing each run
__device__ __align__(16) int    g_rowptr[NN + 1];
__device__ __align__(16) int    g_fill[NN];
__device__ __align__(16) int    g_blocksum[NBLK];
__device__ __align__(16) float  g_dinv[NN];
__device__ __align__(16) int    g_src[EE];
__device__ __align__(16) int    g_dst[EE];
__device__ __align__(16) int2   g_csr_sn[EE];              // {src, norm bits}
__device__ __align__(16) __half g_w1h[128 * 128];
__device__ __align__(16) __half g_w2h[128 * 64];
__device__ __align__(16) __half g_h1h[(size_t)NN * 128];   // fp16 layer-1 linear out
__device__ __align__(16) __half g_h2h[(size_t)NN * 64];    // fp16 layer-2 linear out

// ---------------- side stream + events (static init) ----------------
struct SideStream {
    cudaStream_t s;
    cudaEvent_t evFork, evJoin;
    SideStream() {
        cudaStreamCreateWithFlags(&s, cudaStreamNonBlocking);
        cudaEventCreateWithFlags(&evFork, cudaEventDisableTiming);
        cudaEventCreateWithFlags(&evJoin, cudaEventDisableTiming);
    }
};
static SideStream g_ss;

union H4U { uint2 u; __half2 h[2]; };

// ---------------- edge decode, 4 edges/thread (MLP), degree histogram ----------------
__global__ void prep_edges(const void* __restrict__ ei,
                           int* __restrict__ src, int* __restrict__ dst,
                           int* __restrict__ hist, int nE, int n) {
    int i = blockIdx.x * blockDim.x + threadIdx.x;
    int e0 = i * 4;
    if (e0 >= nE) return;
    const int* w = (const int*)ei;
    bool is64 = (w[1] == 0) & (w[3] == 0) & (w[5] == 0) & (w[7] == 0);
    int s[4], d[4];
    int cnt = min(4, nE - e0);
    if (is64) {
        const long long* p = (const long long*)ei;
#pragma unroll
        for (int j = 0; j < 4; j++) {
            int e = e0 + j;
            if (j < cnt) { s[j] = (int)p[e]; d[j] = (int)p[nE + e]; }
        }
    } else {
#pragma unroll
        for (int j = 0; j < 4; j++) {
            int e = e0 + j;
            if (j < cnt) { s[j] = w[e]; d[j] = w[nE + e]; }
        }
    }
#pragma unroll
    for (int j = 0; j < 4; j++) {
        if (j < cnt) {
            s[j] = min(max(s[j], 0), n - 1);
            d[j] = min(max(d[j], 0), n - 1);
            src[e0 + j] = s[j];
            dst[e0 + j] = d[j];
        }
    }
#pragma unroll
    for (int j = 0; j < 4; j++)
        if (j < cnt) atomicAdd(&hist[d[j]], 1);
}

// ---------------- scan phase 1: per-block exclusive scan (+dinv, hist self-zero) ----------------
__global__ void block_scan(int* __restrict__ hist, int* __restrict__ rowptr,
                           int* __restrict__ blocksum, float* __restrict__ dinv, int n) {
    __shared__ int warpsum[32];
    int t = threadIdx.x, lane = t & 31, wid = t >> 5;
    int idx = blockIdx.x * SCAN_B + t;
    int v = (idx < n) ? hist[idx] : 0;
    if (idx < n) {
        dinv[idx] = rsqrtf(1.0f + (float)v);
        hist[idx] = 0;   // self-zero for next graph replay
    }
    int x = v;
#pragma unroll
    for (int off = 1; off < 32; off <<= 1) {
        int y = __shfl_up_sync(0xffffffff, x, off);
        if (lane >= off) x += y;
    }
    if (lane == 31) warpsum[wid] = x;
    __syncthreads();
    if (wid == 0) {
        int s = warpsum[lane];
#pragma unroll
        for (int off = 1; off < 32; off <<= 1) {
            int y = __shfl_up_sync(0xffffffff, s, off);
            if (lane >= off) s += y;
        }
        warpsum[lane] = s;
    }
    __syncthreads();
    int warpoff = (wid > 0) ? warpsum[wid - 1] : 0;
    int excl = x + warpoff - v;
    if (idx < n) rowptr[idx] = excl;
    if (t == SCAN_B - 1) blocksum[blockIdx.x] = x + warpoff;
}

// ---------------- scan phase 2 (merged): each block scans blocksums + applies offset ----------------
__global__ void finalize_scan(const int* __restrict__ blocksum, int* __restrict__ rowptr,
                              int* __restrict__ fill, int n, int nblk) {
    __shared__ int s_off;
    int b = blockIdx.x;
    int t = threadIdx.x;
    if (t < 32) {
        int acc = 0;
        for (int i = t; i < b; i += 32) acc += blocksum[i];
#pragma unroll
        for (int off = 16; off; off >>= 1) acc += __shfl_down_sync(0xffffffff, acc, off);
        if (t == 0) s_off = acc;
    }
    __syncthreads();
    int off = s_off;
    int idx = b * SCAN_B + t;
    if (idx < n) {
        int p = rowptr[idx] + off;
        rowptr[idx] = p;
        fill[idx] = p;
    }
    if (b == nblk - 1 && t == 0) rowptr[n] = off + blocksum[nblk - 1];
}

// ---------------- CSR fill, 4 edges/thread (MLP) ----------------
__global__ void fill_csr(const int* __restrict__ src, const int* __restrict__ dst,
                         const float* __restrict__ dinv, int* __restrict__ fill,
                         int2* __restrict__ csr_sn, int nE) {
    int i = blockIdx.x * blockDim.x + threadIdx.x;
    int e0 = i * 4;
    if (e0 >= nE) return;
    int cnt = min(4, nE - e0);
    int s[4], d[4];
    // batch index loads (coalesced)
#pragma unroll
    for (int j = 0; j < 4; j++)
        if (j < cnt) { s[j] = src[e0 + j]; d[j] = dst[e0 + j]; }
    // batch dinv gathers (8 independent)
    float ds[4], dd[4];
#pragma unroll
    for (int j = 0; j < 4; j++)
        if (j < cnt) { ds[j] = __ldg(dinv + s[j]); dd[j] = __ldg(dinv + d[j]); }
    // batch atomics (4 independent)
    int pos[4];
#pragma unroll
    for (int j = 0; j < 4; j++)
        if (j < cnt) pos[j] = atomicAdd(&fill[d[j]], 1);
    // batch stores
#pragma unroll
    for (int j = 0; j < 4; j++)
        if (j < cnt) csr_sn[pos[j]] = make_int2(s[j], __float_as_int(ds[j] * dd[j]));
}

// ---------------- weight conversion fp32 -> fp16 ----------------
__global__ void convert_w(const float* __restrict__ W1, const float* __restrict__ W2,
                          __half* __restrict__ W1h, __half* __restrict__ W2h) {
    int i = blockIdx.x * blockDim.x + threadIdx.x;
    if (i < 128 * 128 / 2) {
        float2 f = ((const float2*)W1)[i];
        ((__half2*)W1h)[i] = __floats2half2_rn(f.x, f.y);
    }
    if (i < 128 * 64 / 2) {
        float2 f = ((const float2*)W2)[i];
        ((__half2*)W2h)[i] = __floats2half2_rn(f.x, f.y);
    }
}

// ---------------- WMMA GEMM: Hh[n,128] = X[n,128](->fp16) @ W1h[128,128] ----------------
__global__ void gemm128_wmma(const float* __restrict__ X, const __half* __restrict__ Wh,
                             __half* __restrict__ Hh, int n) {
    __shared__ __align__(16) char smbuf[64 * 132 * 4];   // 33792 B
    __half* As = (__half*)smbuf;     // pitch 136 halves
    float*  Cs = (float*)smbuf;      // pitch 132 floats
    int tid = threadIdx.x;
    int warp = tid >> 5;
    int rowBase = blockIdx.x * 64;

    for (int idx = tid; idx < 64 * 32; idx += 256) {   // float4 units
        int r = idx >> 5, c4 = idx & 31;
        int row = rowBase + r;
        float4 v = (row < n) ? ((const float4*)(X + (size_t)row * 128))[c4]
                             : make_float4(0.f, 0.f, 0.f, 0.f);
        __half2* dst = (__half2*)(As + r * 136 + c4 * 4);
        dst[0] = __floats2half2_rn(v.x, v.y);
        dst[1] = __floats2half2_rn(v.z, v.w);
    }
    __syncthreads();

    int strip = warp >> 1;
    int colHalf = warp & 1;
    wmma::fragment<wmma::accumulator, 16, 16, 16, float> c[4];
#pragma unroll
    for (int i = 0; i < 4; i++) wmma::fill_fragment(c[i], 0.f);

#pragma unroll
    for (int k16 = 0; k16 < 8; k16++) {
        wmma::fragment<wmma::matrix_a, 16, 16, 16, __half, wmma::row_major> a;
        wmma::load_matrix_sync(a, As + strip * 16 * 136 + k16 * 16, 136);
#pragma unroll
        for (int i = 0; i < 4; i++) {
            wmma::fragment<wmma::matrix_b, 16, 16, 16, __half, wmma::row_major> b;
            int ncol = colHalf * 64 + i * 16;
            wmma::load_matrix_sync(b, Wh + k16 * 16 * 128 + ncol, 128);
            wmma::mma_sync(c[i], a, b, c[i]);
        }
    }
    __syncthreads();

#pragma unroll
    for (int i = 0; i < 4; i++) {
        int ncol = colHalf * 64 + i * 16;
        wmma::store_matrix_sync(Cs + strip * 16 * 132 + ncol, c[i], 132, wmma::mem_row_major);
    }
    __syncthreads();

    __half2* H2 = (__half2*)Hh;   // row = 64 half2
    for (int idx = tid; idx < 64 * 64; idx += 256) {
        int r = idx >> 6, c2 = idx & 63;
        int row = rowBase + r;
        if (row < n) {
            float2 f = ((const float2*)(Cs + r * 132))[c2];
            H2[(size_t)row * 64 + c2] = __floats2half2_rn(f.x, f.y);
        }
    }
}

// ---------------- FUSED: aggregate layer1 + WMMA gemm64 ----------------
__global__ void agg_gemm64_fused(const __half* __restrict__ Hh, const int* __restrict__ rowptr,
                                 const int2* __restrict__ csr_sn,
                                 const float* __restrict__ dinv, const float* __restrict__ bias,
                                 const __half* __restrict__ Wh, __half* __restrict__ Hout, int n) {
    __shared__ __align__(16) char smbuf[64 * 136 * 2];   // 17408 B
    __half* As = (__half*)smbuf;     // pitch 136 halves
    float*  Cs = (float*)smbuf;      // pitch 68 floats
    int tid = threadIdx.x;
    int warp = tid >> 5;
    int lane = tid & 31;
    int rowBase = blockIdx.x * 64;

    // ---- phase 1: aggregate 8 nodes per warp ----
    const uint2* H8 = (const uint2*)Hh;
    float4 b4 = ((const float4*)bias)[lane];   // lane's 4 channels
#pragma unroll 1
    for (int i = 0; i < 8; i++) {
        int r = warp * 8 + i;
        int node = rowBase + r;
        float4 acc;
        if (node < n) {
            int beg = rowptr[node], end = rowptr[node + 1];
            float di = dinv[node];
            float selfw = di * di;

            H4U sf; sf.u = __ldg(H8 + (size_t)node * 32 + lane);
            float2 s0 = __half22float2(sf.h[0]);
            float2 s1 = __half22float2(sf.h[1]);
            acc = make_float4(s0.x * selfw, s0.y * selfw, s1.x * selfw, s1.y * selfw);

            int e = beg;
            for (; e + 4 <= end; e += 4) {
                int2 a0 = __ldg(csr_sn + e + 0);
                int2 a1 = __ldg(csr_sn + e + 1);
                int2 a2 = __ldg(csr_sn + e + 2);
                int2 a3 = __ldg(csr_sn + e + 3);
                H4U u0, u1, u2, u3;
                u0.u = __ldg(H8 + (size_t)a0.x * 32 + lane);
                u1.u = __ldg(H8 + (size_t)a1.x * 32 + lane);
                u2.u = __ldg(H8 + (size_t)a2.x * 32 + lane);
                u3.u = __ldg(H8 + (size_t)a3.x * 32 + lane);
                float w0 = __int_as_float(a0.y), w1 = __int_as_float(a1.y);
                float w2 = __int_as_float(a2.y), w3 = __int_as_float(a3.y);
                float2 f;
                f = __half22float2(u0.h[0]); acc.x += f.x * w0; acc.y += f.y * w0;
                f = __half22float2(u0.h[1]); acc.z += f.x * w0; acc.w += f.y * w0;
                f = __half22float2(u1.h[0]); acc.x += f.x * w1; acc.y += f.y * w1;
                f = __half22float2(u1.h[1]); acc.z += f.x * w1; acc.w += f.y * w1;
                f = __half22float2(u2.h[0]); acc.x += f.x * w2; acc.y += f.y * w2;
                f = __half22float2(u2.h[1]); acc.z += f.x * w2; acc.w += f.y * w2;
                f = __half22float2(u3.h[0]); acc.x += f.x * w3; acc.y += f.y * w3;
                f = __half22float2(u3.h[1]); acc.z += f.x * w3; acc.w += f.y * w3;
            }
            for (; e < end; e++) {
                int2 a = __ldg(csr_sn + e);
                float w = __int_as_float(a.y);
                H4U u; u.u = __ldg(H8 + (size_t)a.x * 32 + lane);
                float2 f;
                f = __half22float2(u.h[0]); acc.x += f.x * w; acc.y += f.y * w;
                f = __half22float2(u.h[1]); acc.z += f.x * w; acc.w += f.y * w;
            }
            acc.x = fmaxf(acc.x + b4.x, 0.f);
            acc.y = fmaxf(acc.y + b4.y, 0.f);
            acc.z = fmaxf(acc.z + b4.z, 0.f);
            acc.w = fmaxf(acc.w + b4.w, 0.f);
        } else {
            acc = make_float4(0.f, 0.f, 0.f, 0.f);
        }
        H4U pk;
        pk.h[0] = __floats2half2_rn(acc.x, acc.y);
        pk.h[1] = __floats2half2_rn(acc.z, acc.w);
        *(uint2*)(As + r * 136 + lane * 4) = pk.u;
    }
    __syncthreads();

    // ---- phase 2: WMMA 64x64x128 on As @ Wh ----
    int strip = warp >> 1;
    int colPair = warp & 1;
    wmma::fragment<wmma::accumulator, 16, 16, 16, float> c[2];
#pragma unroll
    for (int i = 0; i < 2; i++) wmma::fill_fragment(c[i], 0.f);

#pragma unroll
    for (int k16 = 0; k16 < 8; k16++) {
        wmma::fragment<wmma::matrix_a, 16, 16, 16, __half, wmma::row_major> a;
        wmma::load_matrix_sync(a, As + strip * 16 * 136 + k16 * 16, 136);
#pragma unroll
        for (int i = 0; i < 2; i++) {
            wmma::fragment<wmma::matrix_b, 16, 16, 16, __half, wmma::row_major> b;
            int ncol = colPair * 32 + i * 16;
            wmma::load_matrix_sync(b, Wh + k16 * 16 * 64 + ncol, 64);
            wmma::mma_sync(c[i], a, b, c[i]);
        }
    }
    __syncthreads();

#pragma unroll
    for (int i = 0; i < 2; i++) {
        int ncol = colPair * 32 + i * 16;
        wmma::store_matrix_sync(Cs + strip * 16 * 68 + ncol, c[i], 68, wmma::mem_row_major);
    }
    __syncthreads();

    __half2* H2 = (__half2*)Hout;   // row = 32 half2
    for (int idx = tid; idx < 64 * 32; idx += 256) {
        int r = idx >> 5, c2 = idx & 31;
        int row = rowBase + r;
        if (row < n) {
            float2 f = ((const float2*)(Cs + r * 68))[c2];
            H2[(size_t)row * 32 + c2] = __floats2half2_rn(f.x, f.y);
        }
    }
}

// ---------------- aggregate layer 2: fp16 gather, fp32 accum, fused ----------------
__global__ void aggregate64(const __half* __restrict__ Hh, const int* __restrict__ rowptr,
                            const int2* __restrict__ csr_sn,
                            const float* __restrict__ dinv, const float* __restrict__ bias,
                            float* __restrict__ out, int n) {
    int node = blockIdx.x * (blockDim.x >> 5) + (threadIdx.x >> 5);
    if (node >= n) return;
    int lane = threadIdx.x & 31;
    int beg = rowptr[node], end = rowptr[node + 1];
    float di = dinv[node];
    float selfw = di * di;

    const __half2* H2h = (const __half2*)Hh;
    float2 sf = __half22float2(__ldg(H2h + (size_t)node * 32 + lane));
    float2 acc = make_float2(sf.x * selfw, sf.y * selfw);

    int e = beg;
    for (; e + 4 <= end; e += 4) {
        int2 a0 = __ldg(csr_sn + e + 0);
        int2 a1 = __ldg(csr_sn + e + 1);
        int2 a2 = __ldg(csr_sn + e + 2);
        int2 a3 = __ldg(csr_sn + e + 3);
        float2 v0 = __half22float2(__ldg(H2h + (size_t)a0.x * 32 + lane));
        float2 v1 = __half22float2(__ldg(H2h + (size_t)a1.x * 32 + lane));
        float2 v2 = __half22float2(__ldg(H2h + (size_t)a2.x * 32 + lane));
        float2 v3 = __half22float2(__ldg(H2h + (size_t)a3.x * 32 + lane));
        float w0 = __int_as_float(a0.y), w1 = __int_as_float(a1.y);
        float w2 = __int_as_float(a2.y), w3 = __int_as_float(a3.y);
        acc.x += v0.x * w0; acc.y += v0.y * w0;
        acc.x += v1.x * w1; acc.y += v1.y * w1;
        acc.x += v2.x * w2; acc.y += v2.y * w2;
        acc.x += v3.x * w3; acc.y += v3.y * w3;
    }
    for (; e < end; e++) {
        int2 a = __ldg(csr_sn + e);
        float w = __int_as_float(a.y);
        float2 v = __half22float2(__ldg(H2h + (size_t)a.x * 32 + lane));
        acc.x += v.x * w; acc.y += v.y * w;
    }
    float2 b = ((const float2*)bias)[lane];
    acc.x += b.x;
    acc.y += b.y;
    ((float2*)out)[(size_t)node * 32 + lane] = acc;
}

// ---------------- launch ----------------
extern "C" void kernel_launch(void* const* d_in, const int* in_sizes, int n_in,
                              void* d_out, int out_size) {
    const float* x  = (const float*)d_in[0];
    const void*  ei = d_in[1];
    const float* W1 = (const float*)d_in[2];
    const float* b1 = (const float*)d_in[3];
    const float* W2 = (const float*)d_in[4];
    const float* b2 = (const float*)d_in[5];
    float* out = (float*)d_out;

    int n  = in_sizes[0] / 128;   // 50000
    int nE = in_sizes[1] / 2;     // 800000

    int *p_hist, *p_rowptr, *p_fill, *p_bsum, *p_src, *p_dst;
    int2* p_csr_sn;
    float *p_dinv;
    __half *p_w1h, *p_w2h, *p_h1h, *p_h2h;
    cudaGetSymbolAddress((void**)&p_hist,   g_hist);
    cudaGetSymbolAddress((void**)&p_rowptr, g_rowptr);
    cudaGetSymbolAddress((void**)&p_fill,   g_fill);
    cudaGetSymbolAddress((void**)&p_bsum,   g_blocksum);
    cudaGetSymbolAddress((void**)&p_dinv,   g_dinv);
    cudaGetSymbolAddress((void**)&p_src,    g_src);
    cudaGetSymbolAddress((void**)&p_dst,    g_dst);
    cudaGetSymbolAddress((void**)&p_csr_sn, g_csr_sn);
    cudaGetSymbolAddress((void**)&p_w1h,    g_w1h);
    cudaGetSymbolAddress((void**)&p_w2h,    g_w2h);
    cudaGetSymbolAddress((void**)&p_h1h,    g_h1h);
    cudaGetSymbolAddress((void**)&p_h2h,    g_h2h);

    const int T = 256;
    int nblk = (n + SCAN_B - 1) / SCAN_B;
    int nquad = (nE + 3) / 4;
    cudaStream_t s2 = g_ss.s;

    // fork: prep chain on side stream, weight-convert + gemm128 on main stream
    cudaEventRecord(g_ss.evFork, 0);
    cudaStreamWaitEvent(s2, g_ss.evFork, 0);

    prep_edges<<<(nquad + T - 1) / T, T, 0, s2>>>(ei, p_src, p_dst, p_hist, nE, n);
    block_scan<<<nblk, SCAN_B, 0, s2>>>(p_hist, p_rowptr, p_bsum, p_dinv, n);
    finalize_scan<<<nblk, SCAN_B, 0, s2>>>(p_bsum, p_rowptr, p_fill, n, nblk);
    fill_csr<<<(nquad + T - 1) / T, T, 0, s2>>>(p_src, p_dst, p_dinv, p_fill, p_csr_sn, nE);
    cudaEventRecord(g_ss.evJoin, s2);

    convert_w<<<32, T>>>(W1, W2, p_w1h, p_w2h);
    gemm128_wmma<<<(n + 63) / 64, T>>>(x, p_w1h, p_h1h, n);   // concurrent with prep

    // join
    cudaStreamWaitEvent(0, g_ss.evJoin, 0);

    agg_gemm64_fused<<<(n + 63) / 64, T>>>(p_h1h, p_rowptr, p_csr_sn, p_dinv, b1,
                                           p_w2h, p_h2h, n);
    aggregate64<<<(n + 7) / 8, T>>>(p_h2h, p_rowptr, p_csr_sn, p_dinv, b2, out, n);
}